// round 12
// baseline (speedup 1.0000x reference)
#include <cuda_runtime.h>
#include <cuda_fp16.h>
#include <cstdint>

// ======================= static device scratch (no allocs allowed) ==========
__device__ __align__(1024) __half g_xh[8192L * 4096];  // x in fp16
__device__ __align__(1024) __half g_qh[4096L * 4096];  // Wc = Q + L@R (fp16)
__device__ __align__(1024) __half g_rt[4096L * 256];   // dequant R, transposed [in, rank]
__device__ __align__(1024) __half g_lh[4096L * 256];   // dequant L fp16

// ======================= PTX helpers (sm_80-level only) =====================
__device__ __forceinline__ uint32_t smem_u32(const void* p) {
    return (uint32_t)__cvta_generic_to_shared(p);
}
__device__ __forceinline__ void cpa16(uint32_t s, const void* g) {
    asm volatile("cp.async.cg.shared.global [%0], [%1], 16;" :: "r"(s), "l"(g) : "memory");
}
#define CPA_COMMIT() asm volatile("cp.async.commit_group;" ::: "memory")
#define CPA_WAIT0()  asm volatile("cp.async.wait_group 0;" ::: "memory")

__device__ __forceinline__ void ldsm4(uint32_t& r0, uint32_t& r1, uint32_t& r2,
                                      uint32_t& r3, uint32_t addr) {
    asm volatile("ldmatrix.sync.aligned.m8n8.x4.shared.b16 {%0,%1,%2,%3}, [%4];"
                 : "=r"(r0), "=r"(r1), "=r"(r2), "=r"(r3) : "r"(addr));
}
__device__ __forceinline__ void mma16816(float* c, uint32_t a0, uint32_t a1,
                                         uint32_t a2, uint32_t a3,
                                         uint32_t b0, uint32_t b1) {
    asm volatile(
        "mma.sync.aligned.m16n8k16.row.col.f32.f16.f16.f32 "
        "{%0,%1,%2,%3}, {%4,%5,%6,%7}, {%8,%9}, {%0,%1,%2,%3};"
        : "+f"(c[0]), "+f"(c[1]), "+f"(c[2]), "+f"(c[3])
        : "r"(a0), "r"(a1), "r"(a2), "r"(a3), "r"(b0), "r"(b1));
}

// ======================= SMEM layout ========================================
// BK = 64 halves per chunk: row = 128B data + 16B pad = 144B.
static constexpr int ROWB       = 144;
static constexpr int OFF_BIAS   = 0;      // 64 floats
static constexpr int OFF_STAGES = 1024;
static constexpr int A_BYTES    = 128 * ROWB;            // 18432 (128 rows)
static constexpr int B_BYTES    = 64 * ROWB;             // 9216  (64 rows)
static constexpr int STAGE_BYTES = A_BYTES + B_BYTES;    // 27648
static constexpr int SMEM_BYTES  = OFF_STAGES + 2 * STAGE_BYTES;  // 56320

// ======================= GEMM kernel ========================================
// C[128,64] = A@B^T over k1c chunks of 64 K. A,B row-major fp16, K contiguous.
// 4 warps (128 threads) in 2x2 grid; warp tile = 64x32 (same validated shape).
// 2-stage cp.async pipeline, 4 CTAs/SM (four independent barrier domains to
// de-phase LDSM bursts from MMA bursts across CTAs).
// Output: float(+bias) to outF, or half to outH (+fused groupwise Q dequant
// when qvals != nullptr; group index (n0>>7) constant per CTA since 64 | 128).
__global__ void __launch_bounds__(128, 4)
gemm_f16_kernel(const __half* __restrict__ A1, const __half* __restrict__ B1,
                int lda1, int ldb1, int k1c,
                const float* __restrict__ bias,
                float* __restrict__ outF, __half* __restrict__ outH,
                const int* __restrict__ qvals, const float* __restrict__ qscales,
                int ldo) {
    extern __shared__ char smem[];
    const int tid    = threadIdx.x;
    const int lane   = tid & 31;
    const int warp   = tid >> 5;
    const int warp_m = warp >> 1;   // 0..1 -> 64-row slab
    const int warp_n = warp & 1;    // 0..1 -> 32-col slab
    const int m0 = blockIdx.y * 128;
    const int n0 = blockIdx.x * 64;
    const uint32_t sb = smem_u32(smem);

    if (tid < 64)
        ((float*)(smem + OFF_BIAS))[tid] = bias ? bias[n0 + tid] : 0.0f;

    const int total = k1c;

    // ---- per-thread loader geometry: (row r0 + 16*i, 16B col c) ----
    const int r0 = tid >> 3;             // 0..15
    const int c  = tid & 7;              // 0..7 (16B units across 128B row)
    const char* gA = (const char*)(A1 + (size_t)(m0 + r0) * lda1) + c * 16;
    const char* gB = (const char*)(B1 + (size_t)(n0 + r0) * ldb1) + c * 16;
    const size_t gstepA = (size_t)16 * lda1 * 2;   // 16 rows, bytes
    const size_t gstepB = (size_t)16 * ldb1 * 2;
    const uint32_t s0 = r0 * ROWB + c * 16;

    auto load_stage = [&](int kc, int buf) {
        const uint32_t base = sb + OFF_STAGES + buf * STAGE_BYTES;
        const size_t go = (size_t)kc * 128;   // 64 halves per chunk (bytes)
#pragma unroll
        for (int i = 0; i < 8; i++)           // A: 128 rows
            cpa16(base + s0 + i * (16 * ROWB), gA + go + i * gstepA);
#pragma unroll
        for (int i = 0; i < 4; i++)           // B: 64 rows
            cpa16(base + A_BYTES + s0 + i * (16 * ROWB), gB + go + i * gstepB);
    };

    float acc[4][4][4];
#pragma unroll
    for (int i = 0; i < 4; i++)
#pragma unroll
        for (int j = 0; j < 4; j++)
#pragma unroll
            for (int e = 0; e < 4; e++) acc[i][j][e] = 0.0f;

    // prologue: prefetch stage 0
    load_stage(0, 0);
    CPA_COMMIT();

    // per-lane ldmatrix base offsets (within a stage buffer)
    const uint32_t a_lane = (uint32_t)((warp_m * 64 + (lane & 15)) * ROWB +
                                       (lane >> 4) * 16);
    const int bq = lane >> 3, br = lane & 7;
    const uint32_t b_lane = (uint32_t)((warp_n * 32 + ((bq >> 1) << 3) + br) * ROWB +
                                       (bq & 1) * 16);

    int buf = 0;
    for (int kc = 0; kc < total; kc++) {
        CPA_WAIT0();            // all committed groups done (stage kc ready)
        __syncthreads();        // visibility + all warps past compute(kc-1)
        if (kc + 1 < total) load_stage(kc + 1, buf ^ 1);
        CPA_COMMIT();           // next stage loads during compute below

        const uint32_t sa  = sb + OFF_STAGES + buf * STAGE_BYTES;
        const uint32_t sbB = sa + A_BYTES;
        buf ^= 1;

#pragma unroll
        for (int s = 0; s < 4; s++) {   // four k16 steps in the 64-K chunk
            uint32_t a[4][4];
#pragma unroll
            for (int mt = 0; mt < 4; mt++)
                ldsm4(a[mt][0], a[mt][1], a[mt][2], a[mt][3],
                      sa + a_lane + (uint32_t)(mt * 16 * ROWB + s * 32));
            uint32_t b[4][2];
#pragma unroll
            for (int nt2 = 0; nt2 < 2; nt2++)
                ldsm4(b[nt2 * 2][0], b[nt2 * 2][1], b[nt2 * 2 + 1][0], b[nt2 * 2 + 1][1],
                      sbB + b_lane + (uint32_t)(nt2 * 16 * ROWB + s * 32));
#pragma unroll
            for (int mt = 0; mt < 4; mt++)
#pragma unroll
                for (int nt = 0; nt < 4; nt++)
                    mma16816(acc[mt][nt], a[mt][0], a[mt][1], a[mt][2], a[mt][3],
                             b[nt][0], b[nt][1]);
        }
    }

    // ---- epilogue ----
    const int g  = lane >> 2;
    const int c2 = (lane & 3) * 2;
    const float* sbias = (const float*)(smem + OFF_BIAS);
    const int qgrp = n0 >> 7;   // constant per CTA (64 | group size 128)
#pragma unroll
    for (int mt = 0; mt < 4; mt++) {
#pragma unroll
        for (int h = 0; h < 2; h++) {
            const int row = m0 + warp_m * 64 + mt * 16 + g + h * 8;
            const float qsc = qvals ? qscales[row * 32 + qgrp] : 0.0f;
#pragma unroll
            for (int nt = 0; nt < 4; nt++) {
                const int coll = warp_n * 32 + nt * 8 + c2;  // col within tile
                float v0 = acc[mt][nt][h * 2 + 0];
                float v1 = acc[mt][nt][h * 2 + 1];
                if (outF) {
                    float2 o;
                    o.x = v0 + sbias[coll];
                    o.y = v1 + sbias[coll + 1];
                    *(float2*)(outF + (size_t)row * ldo + n0 + coll) = o;
                } else {
                    if (qvals) {
                        int2 q = *(const int2*)(qvals + (size_t)row * ldo + n0 + coll);
                        v0 += (float)q.x * qsc;
                        v1 += (float)q.y * qsc;
                    }
                    *(__half2*)(outH + (size_t)row * ldo + n0 + coll) =
                        __floats2half2_rn(v0, v1);
                }
            }
        }
    }
}

// ======================= prologue kernels ===================================
__global__ void cvt_x_kernel(const float* __restrict__ x, __half* __restrict__ o, int n4) {
    int i = blockIdx.x * blockDim.x + threadIdx.x;
    if (i >= n4) return;
    float4 f = ((const float4*)x)[i];
    ((__half2*)o)[2 * i + 0] = __floats2half2_rn(f.x, f.y);
    ((__half2*)o)[2 * i + 1] = __floats2half2_rn(f.z, f.w);
}

// blocks [0,1024): dequant L (4096x256, group 128, row len 256)
// blocks [1024,2048): dequant+transpose R -> rt [4096,256]
__global__ void __launch_bounds__(256)
prologue_kernel(const int* __restrict__ lv, const float* __restrict__ ls,
                __half* __restrict__ lh,
                const int* __restrict__ rv, const float* __restrict__ rs,
                __half* __restrict__ rt) {
    const int tid = threadIdx.x;
    if (blockIdx.x < 1024) {
        int i = blockIdx.x * 256 + tid;          // quad index
        int4 q = ((const int4*)lv)[i];
        int e0 = i << 2;
        int row = e0 >> 8;
        int col = e0 & 255;
        float sc = ls[(row << 1) + (col >> 7)];
        ((__half2*)lh)[2 * i + 0] = __floats2half2_rn((float)q.x * sc, (float)q.y * sc);
        ((__half2*)lh)[2 * i + 1] = __floats2half2_rn((float)q.z * sc, (float)q.w * sc);
    } else {
        __shared__ float tile[32][33];
        const int b  = blockIdx.x - 1024;
        const int i0 = (b & 127) * 32;  // in-dim block
        const int r0 = (b >> 7) * 32;   // rank block
        const int tx = tid & 31, ty = tid >> 5;  // 32 x 8
#pragma unroll
        for (int j = 0; j < 4; j++) {
            int r = r0 + ty + j * 8;
            int i = i0 + tx;
            float sc = rs[r * 32 + (i >> 7)];
            tile[ty + j * 8][tx] = (float)rv[(size_t)r * 4096 + i] * sc;
        }
        __syncthreads();
#pragma unroll
        for (int j = 0; j < 4; j++) {
            int i = i0 + ty + j * 8;
            int r = r0 + tx;
            rt[(size_t)i * 256 + r] = __float2half_rn(tile[tx][ty + j * 8]);
        }
    }
}

// ======================= launch =============================================
extern "C" void kernel_launch(void* const* d_in, const int* in_sizes, int n_in,
                              void* d_out, int out_size) {
    const float* x    = (const float*)d_in[0];
    const int*   qv   = (const int*)d_in[1];
    const float* qs   = (const float*)d_in[2];
    const int*   lv   = (const int*)d_in[3];
    const float* ls   = (const float*)d_in[4];
    const int*   rv   = (const int*)d_in[5];
    const float* rs   = (const float*)d_in[6];
    const float* bias = (const float*)d_in[7];
    float* out = (float*)d_out;

    __half *xh, *qh, *rt, *lh;
    cudaGetSymbolAddress((void**)&xh, g_xh);
    cudaGetSymbolAddress((void**)&qh, g_qh);
    cudaGetSymbolAddress((void**)&rt, g_rt);
    cudaGetSymbolAddress((void**)&lh, g_lh);

    cudaFuncSetAttribute(gemm_f16_kernel,
                         cudaFuncAttributeMaxDynamicSharedMemorySize, SMEM_BYTES);

    // small prologue (one launch) + x convert
    prologue_kernel<<<2048, 256>>>(lv, ls, lh, rv, rs, rt);
    {
        int n4 = 8192 * 4096 / 4;
        cvt_x_kernel<<<n4 / 256, 256>>>(x, xh, n4);
    }

    // qh = dequant(Q) + lh @ rt^T  (M=4096, N=4096, K=256), Q fused in epilogue
    gemm_f16_kernel<<<dim3(64, 32), 128, SMEM_BYTES>>>(
        lh, rt, 256, 256, 4,
        nullptr, nullptr, qh, qv, qs, 4096);

    // y = xh @ Wc^T + bias  (M=8192, N=4096, K=4096)
    gemm_f16_kernel<<<dim3(64, 64), 128, SMEM_BYTES>>>(
        xh, qh, 4096, 4096, 64,
        bias, out, nullptr, nullptr, nullptr, 4096);
}

// round 13
// speedup vs baseline: 1.0687x; 1.0687x over previous
#include <cuda_runtime.h>
#include <cuda_fp16.h>
#include <cstdint>

// ======================= static device scratch (no allocs allowed) ==========
__device__ __align__(1024) __half g_xh[8192L * 4096];  // x in fp16
__device__ __align__(1024) __half g_qh[4096L * 4096];  // Wc = Q + L@R (fp16)
__device__ __align__(1024) __half g_rt[4096L * 256];   // dequant R, transposed [in, rank]
__device__ __align__(1024) __half g_lh[4096L * 256];   // dequant L fp16

// ======================= PTX helpers (sm_80-level only) =====================
__device__ __forceinline__ uint32_t smem_u32(const void* p) {
    return (uint32_t)__cvta_generic_to_shared(p);
}
__device__ __forceinline__ void cpa16(uint32_t s, const void* g) {
    asm volatile("cp.async.cg.shared.global [%0], [%1], 16;" :: "r"(s), "l"(g) : "memory");
}
#define CPA_COMMIT() asm volatile("cp.async.commit_group;" ::: "memory")
#define CPA_WAIT1()  asm volatile("cp.async.wait_group 1;" ::: "memory")

__device__ __forceinline__ void ldsm4(uint32_t& r0, uint32_t& r1, uint32_t& r2,
                                      uint32_t& r3, uint32_t addr) {
    asm volatile("ldmatrix.sync.aligned.m8n8.x4.shared.b16 {%0,%1,%2,%3}, [%4];"
                 : "=r"(r0), "=r"(r1), "=r"(r2), "=r"(r3) : "r"(addr));
}
__device__ __forceinline__ void mma16816(float* c, uint32_t a0, uint32_t a1,
                                         uint32_t a2, uint32_t a3,
                                         uint32_t b0, uint32_t b1) {
    asm volatile(
        "mma.sync.aligned.m16n8k16.row.col.f32.f16.f16.f32 "
        "{%0,%1,%2,%3}, {%4,%5,%6,%7}, {%8,%9}, {%0,%1,%2,%3};"
        : "+f"(c[0]), "+f"(c[1]), "+f"(c[2]), "+f"(c[3])
        : "r"(a0), "r"(a1), "r"(a2), "r"(a3), "r"(b0), "r"(b1));
}

// ======================= SMEM layout ========================================
// BK = 64 halves per chunk: row = 128B data + 16B pad = 144B.
static constexpr int ROWB       = 144;
static constexpr int OFF_BIAS   = 0;      // 128 floats
static constexpr int OFF_STAGES = 1024;
static constexpr int A_BYTES    = 128 * ROWB;   // 18432
static constexpr int STAGE_BYTES = 2 * A_BYTES; // 36864
static constexpr int SMEM_BYTES  = OFF_STAGES + 3 * STAGE_BYTES; // 111616

// ======================= GEMM kernel (R8 shape: 8 warps 2x4, BK=64) =========
// C[128,128] = A@B^T over k1c chunks of 64 K. A,B row-major fp16, K contiguous.
// Output: float(+bias) to outF, or half to outH (+fused groupwise Q dequant
// when qvals != nullptr). 3-stage cp.async pipeline, 2 CTAs/SM.
__global__ void __launch_bounds__(256, 2)
gemm_f16_kernel(const __half* __restrict__ A1, const __half* __restrict__ B1,
                int lda1, int ldb1, int k1c,
                const float* __restrict__ bias,
                float* __restrict__ outF, __half* __restrict__ outH,
                const int* __restrict__ qvals, const float* __restrict__ qscales,
                int ldo) {
    extern __shared__ char smem[];
    const int tid    = threadIdx.x;
    const int lane   = tid & 31;
    const int warp   = tid >> 5;
    const int warp_m = warp >> 2;   // 0..1  -> 64-row slab
    const int warp_n = warp & 3;    // 0..3  -> 32-col slab
    const int m0 = blockIdx.y * 128;
    const int n0 = blockIdx.x * 128;
    const uint32_t sb = smem_u32(smem);

    if (tid < 128)
        ((float*)(smem + OFF_BIAS))[tid] = bias ? bias[n0 + tid] : 0.0f;

    const int total = k1c;

    // ---- per-thread loader geometry: (row r0 + 32*i, 16B col c), i = 0..3 ----
    const int r0 = tid >> 3;             // 0..31
    const int c  = tid & 7;              // 0..7 (16B units across 128B row)
    const char* gA = (const char*)(A1 + (size_t)(m0 + r0) * lda1) + c * 16;
    const char* gB = (const char*)(B1 + (size_t)(n0 + r0) * ldb1) + c * 16;
    const size_t gstepA = (size_t)32 * lda1 * 2;   // 32 rows, bytes
    const size_t gstepB = (size_t)32 * ldb1 * 2;
    const uint32_t s0 = r0 * ROWB + c * 16;

    auto load_stage = [&](int kc, int buf) {
        const uint32_t base = sb + OFF_STAGES + buf * STAGE_BYTES;
        const size_t go = (size_t)kc * 128;   // 64 halves per chunk (bytes)
#pragma unroll
        for (int i = 0; i < 4; i++)
            cpa16(base + s0 + i * (32 * ROWB), gA + go + i * gstepA);
#pragma unroll
        for (int i = 0; i < 4; i++)
            cpa16(base + A_BYTES + s0 + i * (32 * ROWB), gB + go + i * gstepB);
    };

    float acc[4][4][4];
#pragma unroll
    for (int i = 0; i < 4; i++)
#pragma unroll
        for (int j = 0; j < 4; j++)
#pragma unroll
            for (int e = 0; e < 4; e++) acc[i][j][e] = 0.0f;

    // prologue: prefetch 2 stages
    load_stage(0, 0); CPA_COMMIT();
    if (total > 1) load_stage(1, 1);
    CPA_COMMIT();

    // per-lane ldmatrix base offsets (within a stage buffer)
    const uint32_t a_lane = (uint32_t)((warp_m * 64 + (lane & 15)) * ROWB +
                                       (lane >> 4) * 16);
    const int bq = lane >> 3, br = lane & 7;
    const uint32_t b_lane = (uint32_t)((warp_n * 32 + ((bq >> 1) << 3) + br) * ROWB +
                                       (bq & 1) * 16);

    int buf = 0, nbuf = 2;  // buffer of kc, buffer for kc+2
    for (int kc = 0; kc < total; kc++) {
        CPA_WAIT1();
        __syncthreads();
        if (kc + 2 < total) load_stage(kc + 2, nbuf);
        CPA_COMMIT();

        const uint32_t sa  = sb + OFF_STAGES + buf * STAGE_BYTES;
        const uint32_t sbB = sa + A_BYTES;
        nbuf = buf;
        buf = (buf == 2) ? 0 : buf + 1;

#pragma unroll
        for (int s = 0; s < 4; s++) {   // four k16 steps in the 64-K chunk
            uint32_t a[4][4];
#pragma unroll
            for (int mt = 0; mt < 4; mt++)
                ldsm4(a[mt][0], a[mt][1], a[mt][2], a[mt][3],
                      sa + a_lane + (uint32_t)(mt * 16 * ROWB + s * 32));
            uint32_t b[4][2];
#pragma unroll
            for (int nt2 = 0; nt2 < 2; nt2++)
                ldsm4(b[nt2 * 2][0], b[nt2 * 2][1], b[nt2 * 2 + 1][0], b[nt2 * 2 + 1][1],
                      sbB + b_lane + (uint32_t)(nt2 * 16 * ROWB + s * 32));
#pragma unroll
            for (int mt = 0; mt < 4; mt++)
#pragma unroll
                for (int nt = 0; nt < 4; nt++)
                    mma16816(acc[mt][nt], a[mt][0], a[mt][1], a[mt][2], a[mt][3],
                             b[nt][0], b[nt][1]);
        }
    }

    // ---- epilogue ----
    const int g  = lane >> 2;
    const int c2 = (lane & 3) * 2;
    const float* sbias = (const float*)(smem + OFF_BIAS);
    const int qgrp = n0 >> 7;   // group index constant per CTA (tile is 128 wide)
#pragma unroll
    for (int mt = 0; mt < 4; mt++) {
#pragma unroll
        for (int h = 0; h < 2; h++) {
            const int row = m0 + warp_m * 64 + mt * 16 + g + h * 8;
            const float qsc = qvals ? qscales[row * 32 + qgrp] : 0.0f;
#pragma unroll
            for (int nt = 0; nt < 4; nt++) {
                const int coll = warp_n * 32 + nt * 8 + c2;  // col within tile
                float v0 = acc[mt][nt][h * 2 + 0];
                float v1 = acc[mt][nt][h * 2 + 1];
                if (outF) {
                    float2 o;
                    o.x = v0 + sbias[coll];
                    o.y = v1 + sbias[coll + 1];
                    *(float2*)(outF + (size_t)row * ldo + n0 + coll) = o;
                } else {
                    if (qvals) {
                        int2 q = *(const int2*)(qvals + (size_t)row * ldo + n0 + coll);
                        v0 += (float)q.x * qsc;
                        v1 += (float)q.y * qsc;
                    }
                    *(__half2*)(outH + (size_t)row * ldo + n0 + coll) =
                        __floats2half2_rn(v0, v1);
                }
            }
        }
    }
}

// ======================= prologue kernels ===================================
__global__ void cvt_x_kernel(const float* __restrict__ x, __half* __restrict__ o, int n4) {
    int i = blockIdx.x * blockDim.x + threadIdx.x;
    if (i >= n4) return;
    float4 f = ((const float4*)x)[i];
    ((__half2*)o)[2 * i + 0] = __floats2half2_rn(f.x, f.y);
    ((__half2*)o)[2 * i + 1] = __floats2half2_rn(f.z, f.w);
}

// blocks [0,1024): dequant L (4096x256, group 128, row len 256)
// blocks [1024,2048): dequant+transpose R -> rt [4096,256]
__global__ void __launch_bounds__(256)
prologue_kernel(const int* __restrict__ lv, const float* __restrict__ ls,
                __half* __restrict__ lh,
                const int* __restrict__ rv, const float* __restrict__ rs,
                __half* __restrict__ rt) {
    const int tid = threadIdx.x;
    if (blockIdx.x < 1024) {
        int i = blockIdx.x * 256 + tid;          // quad index
        int4 q = ((const int4*)lv)[i];
        int e0 = i << 2;
        int row = e0 >> 8;
        int col = e0 & 255;
        float sc = ls[(row << 1) + (col >> 7)];
        ((__half2*)lh)[2 * i + 0] = __floats2half2_rn((float)q.x * sc, (float)q.y * sc);
        ((__half2*)lh)[2 * i + 1] = __floats2half2_rn((float)q.z * sc, (float)q.w * sc);
    } else {
        __shared__ float tile[32][33];
        const int b  = blockIdx.x - 1024;
        const int i0 = (b & 127) * 32;  // in-dim block
        const int r0 = (b >> 7) * 32;   // rank block
        const int tx = tid & 31, ty = tid >> 5;  // 32 x 8
#pragma unroll
        for (int j = 0; j < 4; j++) {
            int r = r0 + ty + j * 8;
            int i = i0 + tx;
            float sc = rs[r * 32 + (i >> 7)];
            tile[ty + j * 8][tx] = (float)rv[(size_t)r * 4096 + i] * sc;
        }
        __syncthreads();
#pragma unroll
        for (int j = 0; j < 4; j++) {
            int i = i0 + ty + j * 8;
            int r = r0 + tx;
            rt[(size_t)i * 256 + r] = __float2half_rn(tile[tx][ty + j * 8]);
        }
    }
}

// ======================= launch =============================================
extern "C" void kernel_launch(void* const* d_in, const int* in_sizes, int n_in,
                              void* d_out, int out_size) {
    const float* x    = (const float*)d_in[0];
    const int*   qv   = (const int*)d_in[1];
    const float* qs   = (const float*)d_in[2];
    const int*   lv   = (const int*)d_in[3];
    const float* ls   = (const float*)d_in[4];
    const int*   rv   = (const int*)d_in[5];
    const float* rs   = (const float*)d_in[6];
    const float* bias = (const float*)d_in[7];
    float* out = (float*)d_out;

    __half *xh, *qh, *rt, *lh;
    cudaGetSymbolAddress((void**)&xh, g_xh);
    cudaGetSymbolAddress((void**)&qh, g_qh);
    cudaGetSymbolAddress((void**)&rt, g_rt);
    cudaGetSymbolAddress((void**)&lh, g_lh);

    cudaFuncSetAttribute(gemm_f16_kernel,
                         cudaFuncAttributeMaxDynamicSharedMemorySize, SMEM_BYTES);

    // lazily-created side stream + fork/join events (host objects only; no
    // device allocation; identical work every call -> deterministic)
    static cudaStream_t s2 = nullptr;
    static cudaEvent_t evFork = nullptr, evJoin = nullptr;
    if (!s2) {
        cudaStreamCreateWithFlags(&s2, cudaStreamNonBlocking);
        cudaEventCreateWithFlags(&evFork, cudaEventDisableTiming);
        cudaEventCreateWithFlags(&evJoin, cudaEventDisableTiming);
    }

    // fork: cvt_x (pure HBM) runs on s2, concurrent with prologue + Wc GEMM
    cudaEventRecord(evFork, 0);
    cudaStreamWaitEvent(s2, evFork, 0);
    {
        int n4 = 8192 * 4096 / 4;
        cvt_x_kernel<<<n4 / 256, 256, 0, s2>>>(x, xh, n4);
    }
    cudaEventRecord(evJoin, s2);

    // main stream: small prologue, then Wc = dequant(Q) + L@R
    prologue_kernel<<<2048, 256>>>(lv, ls, lh, rv, rs, rt);
    gemm_f16_kernel<<<dim3(32, 32), 256, SMEM_BYTES>>>(
        lh, rt, 256, 256, 4,
        nullptr, nullptr, qh, qv, qs, 4096);

    // join: main GEMM needs xh (from s2) and qh
    cudaStreamWaitEvent(0, evJoin, 0);

    // y = xh @ Wc^T + bias  (M=8192, N=4096, K=4096)
    gemm_f16_kernel<<<dim3(32, 64), 256, SMEM_BYTES>>>(
        xh, qh, 4096, 4096, 64,
        bias, out, nullptr, nullptr, nullptr, 4096);
}

// round 14
// speedup vs baseline: 1.0695x; 1.0008x over previous
#include <cuda_runtime.h>
#include <cuda_fp16.h>
#include <cstdint>

// ======================= static device scratch (no allocs allowed) ==========
__device__ __align__(1024) __half g_xh[8192L * 4096];  // x in fp16
__device__ __align__(1024) __half g_qh[4096L * 4096];  // Wc = Q + L@R (fp16)
__device__ __align__(1024) __half g_rt[4096L * 256];   // dequant R, transposed [in, rank]
__device__ __align__(1024) __half g_lh[4096L * 256];   // dequant L fp16

// ======================= PTX helpers (sm_80-level only) =====================
__device__ __forceinline__ uint32_t smem_u32(const void* p) {
    return (uint32_t)__cvta_generic_to_shared(p);
}
__device__ __forceinline__ void cpa16(uint32_t s, const void* g) {
    asm volatile("cp.async.cg.shared.global [%0], [%1], 16;" :: "r"(s), "l"(g) : "memory");
}
#define CPA_COMMIT() asm volatile("cp.async.commit_group;" ::: "memory")
#define CPA_WAIT1()  asm volatile("cp.async.wait_group 1;" ::: "memory")
#define CPA_WAIT0()  asm volatile("cp.async.wait_group 0;" ::: "memory")

__device__ __forceinline__ void ldsm4(uint32_t& r0, uint32_t& r1, uint32_t& r2,
                                      uint32_t& r3, uint32_t addr) {
    asm volatile("ldmatrix.sync.aligned.m8n8.x4.shared.b16 {%0,%1,%2,%3}, [%4];"
                 : "=r"(r0), "=r"(r1), "=r"(r2), "=r"(r3) : "r"(addr));
}
__device__ __forceinline__ void mma16816(float* c, uint32_t a0, uint32_t a1,
                                         uint32_t a2, uint32_t a3,
                                         uint32_t b0, uint32_t b1) {
    asm volatile(
        "mma.sync.aligned.m16n8k16.row.col.f32.f16.f16.f32 "
        "{%0,%1,%2,%3}, {%4,%5,%6,%7}, {%8,%9}, {%0,%1,%2,%3};"
        : "+f"(c[0]), "+f"(c[1]), "+f"(c[2]), "+f"(c[3])
        : "r"(a0), "r"(a1), "r"(a2), "r"(a3), "r"(b0), "r"(b1));
}

// ======================= SMEM layout ========================================
// BK = 64 halves per chunk: row = 128B data + 16B pad = 144B.
static constexpr int ROWB       = 144;
static constexpr int OFF_BIAS   = 0;
static constexpr int OFF_STAGES = 1024;
static constexpr int A_BYTES    = 128 * ROWB;   // 18432
static constexpr int STAGE_BYTES = 2 * A_BYTES; // 36864 (A 128 rows + B 128 rows)
static constexpr int SMEM_BYTES  = OFF_STAGES + 3 * STAGE_BYTES; // 111616

static constexpr int B_BYTES_S   = 64 * ROWB;                 // small variant B
static constexpr int STAGE_S     = A_BYTES + B_BYTES_S;       // 27648
static constexpr int SMEM_SMALL  = OFF_STAGES + 2 * STAGE_S;  // 56320

// ======================= main GEMM kernel (R8 shape, validated plateau) =====
// C[128,128] = A@B^T over k1c chunks of 64 K. 8 warps 2x4, 3-stage, 2 CTAs/SM.
__global__ void __launch_bounds__(256, 2)
gemm_f16_kernel(const __half* __restrict__ A1, const __half* __restrict__ B1,
                int lda1, int ldb1, int k1c,
                const float* __restrict__ bias,
                float* __restrict__ outF, __half* __restrict__ outH,
                const int* __restrict__ qvals, const float* __restrict__ qscales,
                int ldo) {
    extern __shared__ char smem[];
    const int tid    = threadIdx.x;
    const int lane   = tid & 31;
    const int warp   = tid >> 5;
    const int warp_m = warp >> 2;
    const int warp_n = warp & 3;
    const int m0 = blockIdx.y * 128;
    const int n0 = blockIdx.x * 128;
    const uint32_t sb = smem_u32(smem);

    if (tid < 128)
        ((float*)(smem + OFF_BIAS))[tid] = bias ? bias[n0 + tid] : 0.0f;

    const int total = k1c;

    const int r0 = tid >> 3;
    const int c  = tid & 7;
    const char* gA = (const char*)(A1 + (size_t)(m0 + r0) * lda1) + c * 16;
    const char* gB = (const char*)(B1 + (size_t)(n0 + r0) * ldb1) + c * 16;
    const size_t gstepA = (size_t)32 * lda1 * 2;
    const size_t gstepB = (size_t)32 * ldb1 * 2;
    const uint32_t s0 = r0 * ROWB + c * 16;

    auto load_stage = [&](int kc, int buf) {
        const uint32_t base = sb + OFF_STAGES + buf * STAGE_BYTES;
        const size_t go = (size_t)kc * 128;
#pragma unroll
        for (int i = 0; i < 4; i++)
            cpa16(base + s0 + i * (32 * ROWB), gA + go + i * gstepA);
#pragma unroll
        for (int i = 0; i < 4; i++)
            cpa16(base + A_BYTES + s0 + i * (32 * ROWB), gB + go + i * gstepB);
    };

    float acc[4][4][4];
#pragma unroll
    for (int i = 0; i < 4; i++)
#pragma unroll
        for (int j = 0; j < 4; j++)
#pragma unroll
            for (int e = 0; e < 4; e++) acc[i][j][e] = 0.0f;

    load_stage(0, 0); CPA_COMMIT();
    if (total > 1) load_stage(1, 1);
    CPA_COMMIT();

    const uint32_t a_lane = (uint32_t)((warp_m * 64 + (lane & 15)) * ROWB +
                                       (lane >> 4) * 16);
    const int bq = lane >> 3, br = lane & 7;
    const uint32_t b_lane = (uint32_t)((warp_n * 32 + ((bq >> 1) << 3) + br) * ROWB +
                                       (bq & 1) * 16);

    int buf = 0, nbuf = 2;
    for (int kc = 0; kc < total; kc++) {
        CPA_WAIT1();
        __syncthreads();
        if (kc + 2 < total) load_stage(kc + 2, nbuf);
        CPA_COMMIT();

        const uint32_t sa  = sb + OFF_STAGES + buf * STAGE_BYTES;
        const uint32_t sbB = sa + A_BYTES;
        nbuf = buf;
        buf = (buf == 2) ? 0 : buf + 1;

#pragma unroll
        for (int s = 0; s < 4; s++) {
            uint32_t a[4][4];
#pragma unroll
            for (int mt = 0; mt < 4; mt++)
                ldsm4(a[mt][0], a[mt][1], a[mt][2], a[mt][3],
                      sa + a_lane + (uint32_t)(mt * 16 * ROWB + s * 32));
            uint32_t b[4][2];
#pragma unroll
            for (int nt2 = 0; nt2 < 2; nt2++)
                ldsm4(b[nt2 * 2][0], b[nt2 * 2][1], b[nt2 * 2 + 1][0], b[nt2 * 2 + 1][1],
                      sbB + b_lane + (uint32_t)(nt2 * 16 * ROWB + s * 32));
#pragma unroll
            for (int mt = 0; mt < 4; mt++)
#pragma unroll
                for (int nt = 0; nt < 4; nt++)
                    mma16816(acc[mt][nt], a[mt][0], a[mt][1], a[mt][2], a[mt][3],
                             b[nt][0], b[nt][1]);
        }
    }

    const int g  = lane >> 2;
    const int c2 = (lane & 3) * 2;
    const float* sbias = (const float*)(smem + OFF_BIAS);
    const int qgrp = n0 >> 7;
#pragma unroll
    for (int mt = 0; mt < 4; mt++) {
#pragma unroll
        for (int h = 0; h < 2; h++) {
            const int row = m0 + warp_m * 64 + mt * 16 + g + h * 8;
            const float qsc = qvals ? qscales[row * 32 + qgrp] : 0.0f;
#pragma unroll
            for (int nt = 0; nt < 4; nt++) {
                const int coll = warp_n * 32 + nt * 8 + c2;
                float v0 = acc[mt][nt][h * 2 + 0];
                float v1 = acc[mt][nt][h * 2 + 1];
                if (outF) {
                    float2 o;
                    o.x = v0 + sbias[coll];
                    o.y = v1 + sbias[coll + 1];
                    *(float2*)(outF + (size_t)row * ldo + n0 + coll) = o;
                } else {
                    if (qvals) {
                        int2 q = *(const int2*)(qvals + (size_t)row * ldo + n0 + coll);
                        v0 += (float)q.x * qsc;
                        v1 += (float)q.y * qsc;
                    }
                    *(__half2*)(outH + (size_t)row * ldo + n0 + coll) =
                        __floats2half2_rn(v0, v1);
                }
            }
        }
    }
}

// ======================= small-K GEMM kernel (for Wc: latency-optimized) ====
// C[128,64], 4 warps 2x2, 2-stage, 4 CTAs/SM (2048 CTAs for M=N=4096 -> 2x
// concurrency for fill/drain + epilogue latency hiding on short K).
__global__ void __launch_bounds__(128, 4)
gemm_small_kernel(const __half* __restrict__ A1, const __half* __restrict__ B1,
                  int lda1, int ldb1, int k1c,
                  __half* __restrict__ outH,
                  const int* __restrict__ qvals, const float* __restrict__ qscales,
                  int ldo) {
    extern __shared__ char smem[];
    const int tid    = threadIdx.x;
    const int lane   = tid & 31;
    const int warp   = tid >> 5;
    const int warp_m = warp >> 1;
    const int warp_n = warp & 1;
    const int m0 = blockIdx.y * 128;
    const int n0 = blockIdx.x * 64;
    const uint32_t sb = smem_u32(smem);

    const int total = k1c;

    const int r0 = tid >> 3;             // 0..15
    const int c  = tid & 7;
    const char* gA = (const char*)(A1 + (size_t)(m0 + r0) * lda1) + c * 16;
    const char* gB = (const char*)(B1 + (size_t)(n0 + r0) * ldb1) + c * 16;
    const size_t gstepA = (size_t)16 * lda1 * 2;
    const size_t gstepB = (size_t)16 * ldb1 * 2;
    const uint32_t s0 = r0 * ROWB + c * 16;

    auto load_stage = [&](int kc, int buf) {
        const uint32_t base = sb + OFF_STAGES + buf * STAGE_S;
        const size_t go = (size_t)kc * 128;
#pragma unroll
        for (int i = 0; i < 8; i++)           // A: 128 rows
            cpa16(base + s0 + i * (16 * ROWB), gA + go + i * gstepA);
#pragma unroll
        for (int i = 0; i < 4; i++)           // B: 64 rows
            cpa16(base + A_BYTES + s0 + i * (16 * ROWB), gB + go + i * gstepB);
    };

    float acc[4][4][4];
#pragma unroll
    for (int i = 0; i < 4; i++)
#pragma unroll
        for (int j = 0; j < 4; j++)
#pragma unroll
            for (int e = 0; e < 4; e++) acc[i][j][e] = 0.0f;

    load_stage(0, 0);
    CPA_COMMIT();

    const uint32_t a_lane = (uint32_t)((warp_m * 64 + (lane & 15)) * ROWB +
                                       (lane >> 4) * 16);
    const int bq = lane >> 3, br = lane & 7;
    const uint32_t b_lane = (uint32_t)((warp_n * 32 + ((bq >> 1) << 3) + br) * ROWB +
                                       (bq & 1) * 16);

    int buf = 0;
    for (int kc = 0; kc < total; kc++) {
        CPA_WAIT0();
        __syncthreads();
        if (kc + 1 < total) load_stage(kc + 1, buf ^ 1);
        CPA_COMMIT();

        const uint32_t sa  = sb + OFF_STAGES + buf * STAGE_S;
        const uint32_t sbB = sa + A_BYTES;
        buf ^= 1;

#pragma unroll
        for (int s = 0; s < 4; s++) {
            uint32_t a[4][4];
#pragma unroll
            for (int mt = 0; mt < 4; mt++)
                ldsm4(a[mt][0], a[mt][1], a[mt][2], a[mt][3],
                      sa + a_lane + (uint32_t)(mt * 16 * ROWB + s * 32));
            uint32_t b[4][2];
#pragma unroll
            for (int nt2 = 0; nt2 < 2; nt2++)
                ldsm4(b[nt2 * 2][0], b[nt2 * 2][1], b[nt2 * 2 + 1][0], b[nt2 * 2 + 1][1],
                      sbB + b_lane + (uint32_t)(nt2 * 16 * ROWB + s * 32));
#pragma unroll
            for (int mt = 0; mt < 4; mt++)
#pragma unroll
                for (int nt = 0; nt < 4; nt++)
                    mma16816(acc[mt][nt], a[mt][0], a[mt][1], a[mt][2], a[mt][3],
                             b[nt][0], b[nt][1]);
        }
    }

    const int g  = lane >> 2;
    const int c2 = (lane & 3) * 2;
    const int qgrp = n0 >> 7;
#pragma unroll
    for (int mt = 0; mt < 4; mt++) {
#pragma unroll
        for (int h = 0; h < 2; h++) {
            const int row = m0 + warp_m * 64 + mt * 16 + g + h * 8;
            const float qsc = qscales[row * 32 + qgrp];
#pragma unroll
            for (int nt = 0; nt < 4; nt++) {
                const int coll = warp_n * 32 + nt * 8 + c2;
                int2 q = *(const int2*)(qvals + (size_t)row * ldo + n0 + coll);
                float v0 = acc[mt][nt][h * 2 + 0] + (float)q.x * qsc;
                float v1 = acc[mt][nt][h * 2 + 1] + (float)q.y * qsc;
                *(__half2*)(outH + (size_t)row * ldo + n0 + coll) =
                    __floats2half2_rn(v0, v1);
            }
        }
    }
}

// ======================= prologue kernels ===================================
__global__ void cvt_x_kernel(const float* __restrict__ x, __half* __restrict__ o, int n4) {
    int i = blockIdx.x * blockDim.x + threadIdx.x;
    if (i >= n4) return;
    float4 f = ((const float4*)x)[i];
    ((__half2*)o)[2 * i + 0] = __floats2half2_rn(f.x, f.y);
    ((__half2*)o)[2 * i + 1] = __floats2half2_rn(f.z, f.w);
}

__global__ void __launch_bounds__(256)
prologue_kernel(const int* __restrict__ lv, const float* __restrict__ ls,
                __half* __restrict__ lh,
                const int* __restrict__ rv, const float* __restrict__ rs,
                __half* __restrict__ rt) {
    const int tid = threadIdx.x;
    if (blockIdx.x < 1024) {
        int i = blockIdx.x * 256 + tid;
        int4 q = ((const int4*)lv)[i];
        int e0 = i << 2;
        int row = e0 >> 8;
        int col = e0 & 255;
        float sc = ls[(row << 1) + (col >> 7)];
        ((__half2*)lh)[2 * i + 0] = __floats2half2_rn((float)q.x * sc, (float)q.y * sc);
        ((__half2*)lh)[2 * i + 1] = __floats2half2_rn((float)q.z * sc, (float)q.w * sc);
    } else {
        __shared__ float tile[32][33];
        const int b  = blockIdx.x - 1024;
        const int i0 = (b & 127) * 32;
        const int r0 = (b >> 7) * 32;
        const int tx = tid & 31, ty = tid >> 5;
#pragma unroll
        for (int j = 0; j < 4; j++) {
            int r = r0 + ty + j * 8;
            int i = i0 + tx;
            float sc = rs[r * 32 + (i >> 7)];
            tile[ty + j * 8][tx] = (float)rv[(size_t)r * 4096 + i] * sc;
        }
        __syncthreads();
#pragma unroll
        for (int j = 0; j < 4; j++) {
            int i = i0 + ty + j * 8;
            int r = r0 + tx;
            rt[(size_t)i * 256 + r] = __float2half_rn(tile[tx][ty + j * 8]);
        }
    }
}

// ======================= launch =============================================
extern "C" void kernel_launch(void* const* d_in, const int* in_sizes, int n_in,
                              void* d_out, int out_size) {
    const float* x    = (const float*)d_in[0];
    const int*   qv   = (const int*)d_in[1];
    const float* qs   = (const float*)d_in[2];
    const int*   lv   = (const int*)d_in[3];
    const float* ls   = (const float*)d_in[4];
    const int*   rv   = (const int*)d_in[5];
    const float* rs   = (const float*)d_in[6];
    const float* bias = (const float*)d_in[7];
    float* out = (float*)d_out;

    __half *xh, *qh, *rt, *lh;
    cudaGetSymbolAddress((void**)&xh, g_xh);
    cudaGetSymbolAddress((void**)&qh, g_qh);
    cudaGetSymbolAddress((void**)&rt, g_rt);
    cudaGetSymbolAddress((void**)&lh, g_lh);

    cudaFuncSetAttribute(gemm_f16_kernel,
                         cudaFuncAttributeMaxDynamicSharedMemorySize, SMEM_BYTES);
    cudaFuncSetAttribute(gemm_small_kernel,
                         cudaFuncAttributeMaxDynamicSharedMemorySize, SMEM_SMALL);

    static cudaStream_t s2 = nullptr;
    static cudaEvent_t evFork = nullptr, evJoin = nullptr;
    if (!s2) {
        cudaStreamCreateWithFlags(&s2, cudaStreamNonBlocking);
        cudaEventCreateWithFlags(&evFork, cudaEventDisableTiming);
        cudaEventCreateWithFlags(&evJoin, cudaEventDisableTiming);
    }

    // fork: cvt_x (pure HBM) on s2, concurrent with prologue + Wc GEMM
    cudaEventRecord(evFork, 0);
    cudaStreamWaitEvent(s2, evFork, 0);
    {
        int n4 = 8192 * 4096 / 4;
        cvt_x_kernel<<<n4 / 256, 256, 0, s2>>>(x, xh, n4);
    }
    cudaEventRecord(evJoin, s2);

    // main stream: small prologue, then Wc = dequant(Q) + L@R (latency variant)
    prologue_kernel<<<2048, 256>>>(lv, ls, lh, rv, rs, rt);
    gemm_small_kernel<<<dim3(64, 32), 128, SMEM_SMALL>>>(
        lh, rt, 256, 256, 4, qh, qv, qs, 4096);

    // join: main GEMM needs xh (from s2) and qh
    cudaStreamWaitEvent(0, evJoin, 0);

    // y = xh @ Wc^T + bias  (M=8192, N=4096, K=4096)
    gemm_f16_kernel<<<dim3(32, 64), 256, SMEM_BYTES>>>(
        xh, qh, 4096, 4096, 64,
        bias, out, nullptr, nullptr, nullptr, 4096);
}